// round 2
// baseline (speedup 1.0000x reference)
#include <cuda_runtime.h>
#include <math.h>

// ---------------- problem constants ----------------
#define S_LEN   50      // SRC
#define T_LEN   50      // TRG
#define BATCH   32
#define E_DIM   620     // EMBED
#define ECH     1000
#define H_DIM   1000    // DCH
#define A_DIM   2000    // 2*ECH
#define V_DIM   30000   // VOCAB
#define G_DIM   3000    // 3*DCH
#define C2_DIM  3620    // E + H + A
#define NSTEPS  49
#define ROWS    (NSTEPS*BATCH)   // 1568

// ---------------- device scratch ----------------
#define OFF_ATT_PRE 0           // (S*B, H)      ann @ Wc_a.T + b_c
#define OFF_ANN_IH  1600000     // (S*B, 3H)     ann @ Wih_c.T
#define OFF_GI_E    6400000     // (ROWS, 3H)    emb[tok] @ Wih_e.T + b_ih
#define OFF_H       11104000    // (50, B, H)    h_0 .. h_49
#define OFF_COMB2   12704000    // (ROWS, 3620)  [emb | h | ctx]
#define OFF_U       18380160    // (B, H)
#define OFF_GH      18412160    // (B, 3H)
#define OFF_SCORES  18508160    // (S, B)
#define SCRATCH_FLOATS 18509760

__device__ __align__(16) float g_scratch[SCRATCH_FLOATS];

// ---------------- helpers ----------------
__device__ __forceinline__ float warp_sum(float v) {
#pragma unroll
    for (int o = 16; o; o >>= 1) v += __shfl_xor_sync(0xffffffffu, v, o);
    return v;
}
__device__ __forceinline__ float warp_max(float v) {
#pragma unroll
    for (int o = 16; o; o >>= 1) v = fmaxf(v, __shfl_xor_sync(0xffffffffu, v, o));
    return v;
}

// ---------------- tiled fp32 GEMM: C[M,N] = act(A[M,K] @ W[N,K]^T + bias) ----------------
// A row-major (stride lda), W row-major (stride ldw), both K-contiguous.
// Requires K%4==0 and 16B-aligned row bases (true for all call sites).
#define GBM 128
#define GBN 128
#define GBK 8

template<int ACT>   // 0 = none, 1 = tanh
__global__ __launch_bounds__(256)
void gemm_tn_kernel(int M, int N, int K,
                    const float* __restrict__ A, int lda,
                    const float* __restrict__ W, int ldw,
                    const float* __restrict__ bias,
                    float* __restrict__ C, int ldc)
{
    __shared__ float As[GBK][GBM + 4];
    __shared__ float Ws[GBK][GBN + 4];

    const int tid = threadIdx.x;
    const int m0 = blockIdx.y * GBM;
    const int n0 = blockIdx.x * GBN;
    const int tx = tid & 15;
    const int ty = tid >> 4;
    const int lm = tid >> 1;        // 0..127
    const int lk = (tid & 1) * 4;   // 0 or 4

    float acc[8][8];
#pragma unroll
    for (int i = 0; i < 8; i++)
#pragma unroll
        for (int j = 0; j < 8; j++) acc[i][j] = 0.f;

    for (int k0 = 0; k0 < K; k0 += GBK) {
        float4 av = make_float4(0.f, 0.f, 0.f, 0.f);
        if ((m0 + lm) < M && (k0 + lk) < K)
            av = *reinterpret_cast<const float4*>(A + (size_t)(m0 + lm) * lda + k0 + lk);
        As[lk + 0][lm] = av.x; As[lk + 1][lm] = av.y;
        As[lk + 2][lm] = av.z; As[lk + 3][lm] = av.w;

        float4 wv = make_float4(0.f, 0.f, 0.f, 0.f);
        if ((n0 + lm) < N && (k0 + lk) < K)
            wv = *reinterpret_cast<const float4*>(W + (size_t)(n0 + lm) * ldw + k0 + lk);
        Ws[lk + 0][lm] = wv.x; Ws[lk + 1][lm] = wv.y;
        Ws[lk + 2][lm] = wv.z; Ws[lk + 3][lm] = wv.w;

        __syncthreads();

#pragma unroll
        for (int k = 0; k < GBK; k++) {
            float4 a0 = *reinterpret_cast<const float4*>(&As[k][ty * 8]);
            float4 a1 = *reinterpret_cast<const float4*>(&As[k][ty * 8 + 4]);
            float4 b0 = *reinterpret_cast<const float4*>(&Ws[k][tx * 8]);
            float4 b1 = *reinterpret_cast<const float4*>(&Ws[k][tx * 8 + 4]);
            float ar[8] = {a0.x, a0.y, a0.z, a0.w, a1.x, a1.y, a1.z, a1.w};
            float br[8] = {b0.x, b0.y, b0.z, b0.w, b1.x, b1.y, b1.z, b1.w};
#pragma unroll
            for (int i = 0; i < 8; i++)
#pragma unroll
                for (int j = 0; j < 8; j++)
                    acc[i][j] = fmaf(ar[i], br[j], acc[i][j]);
        }
        __syncthreads();
    }

#pragma unroll
    for (int i = 0; i < 8; i++) {
        int m = m0 + ty * 8 + i;
        if (m >= M) continue;
#pragma unroll
        for (int j = 0; j < 8; j++) {
            int n = n0 + tx * 8 + j;
            if (n >= N) continue;
            float v = acc[i][j];
            if (bias) v += bias[n];
            if (ACT == 1) v = tanhf(v);
            C[(size_t)m * ldc + n] = v;
        }
    }
}

// ---------------- init: zero preds[0] and attns[0] ----------------
__global__ void zero_kernel(float* __restrict__ preds, float* __restrict__ attns)
{
    int i = blockIdx.x * blockDim.x + threadIdx.x;
    if (i < BATCH * V_DIM) preds[i] = 0.f;
    if (i < S_LEN * BATCH) attns[i] = 0.f;
}

// ---------------- gather embeddings into comb2 emb columns ----------------
__global__ void gather_kernel(const int* __restrict__ tokens,
                              const float* __restrict__ emb,
                              float* __restrict__ comb2)
{
    int r = blockIdx.x;                 // r = t*BATCH + b  -> tokens[t][b]
    int tok = tokens[r];
    const float4* src = reinterpret_cast<const float4*>(emb + (size_t)tok * E_DIM);
    float4* dst = reinterpret_cast<float4*>(comb2 + (size_t)r * C2_DIM);
    int i = threadIdx.x;
    if (i < E_DIM / 4) dst[i] = src[i];
}

// ---------------- per-step: u = h@Wc_h.T (B,H) and gh = h@W_hh.T (B,3H) ----------------
__global__ void hmats_kernel(const float* __restrict__ h,
                             const float* __restrict__ W_c,
                             const float* __restrict__ W_hh,
                             float* __restrict__ u,
                             float* __restrict__ gh)
{
    int w = (blockIdx.x * blockDim.x + threadIdx.x) >> 5;
    if (w >= BATCH * (H_DIM + G_DIM)) return;
    int lane = threadIdx.x & 31;
    int b = w / (H_DIM + G_DIM);
    int n = w % (H_DIM + G_DIM);
    const float* a = h + (size_t)b * H_DIM;
    const float* wr;
    float* out;
    if (n < H_DIM) { wr = W_c + (size_t)n * (H_DIM + A_DIM); out = u + (size_t)b * H_DIM + n; }
    else { int j = n - H_DIM; wr = W_hh + (size_t)j * H_DIM; out = gh + (size_t)b * G_DIM + j; }
    float s = 0.f;
    const float4* a4 = reinterpret_cast<const float4*>(a);
    const float4* w4 = reinterpret_cast<const float4*>(wr);
#pragma unroll 2
    for (int i = lane; i < H_DIM / 4; i += 32) {
        float4 x = a4[i], y = w4[i];
        s += x.x * y.x + x.y * y.y + x.z * y.z + x.w * y.w;
    }
    s = warp_sum(s);
    if (lane == 0) *out = s;
}

// ---------------- per-step: scores[s,b] = w_a . tanh(att_pre[s,b,:] + u[b,:]) ----------------
__global__ void scores_kernel(const float* __restrict__ att_pre,
                              const float* __restrict__ u,
                              const float* __restrict__ w_a,
                              float* __restrict__ scores)
{
    int w = (blockIdx.x * blockDim.x + threadIdx.x) >> 5;   // s*32+b
    if (w >= S_LEN * BATCH) return;
    int lane = threadIdx.x & 31;
    int b = w & 31;
    const float4* ap = reinterpret_cast<const float4*>(att_pre + (size_t)w * H_DIM);
    const float4* ub = reinterpret_cast<const float4*>(u + (size_t)b * H_DIM);
    const float4* wa = reinterpret_cast<const float4*>(w_a);
    float s = 0.f;
    for (int i = lane; i < H_DIM / 4; i += 32) {
        float4 p = ap[i], q = ub[i], wv = wa[i];
        s += wv.x * tanhf(p.x + q.x) + wv.y * tanhf(p.y + q.y)
           + wv.z * tanhf(p.z + q.z) + wv.w * tanhf(p.w + q.w);
    }
    s = warp_sum(s);
    if (lane == 0) scores[w] = s;
}

// ---------------- per-step: softmax over batch axis + context into comb2 ----------------
__global__ void softmax_ctx_kernel(const float* __restrict__ scores,
                                   const float* __restrict__ ann,
                                   float* __restrict__ attn_out,   // attns[t] (S,B)
                                   float* __restrict__ ctx_out)    // comb2 row block for step
{
    __shared__ float attn_sh[S_LEN * BATCH];
    int tid = threadIdx.x;
    int warp = tid >> 5, lane = tid & 31;       // lane == batch index (B==32)

    for (int s = warp; s < S_LEN; s += 8) {
        float v = scores[s * BATCH + lane];
        float mx = warp_max(v);                 // softmax over batch axis (faithful)
        float e = __expf(v - mx);
        float sm = warp_sum(e);
        float a = e / sm;
        attn_sh[s * BATCH + lane] = a;
        if (blockIdx.x == 0) attn_out[s * BATCH + lane] = a;
    }
    __syncthreads();

    // context: 64 blocks cover BATCH*A_DIM = 64000 elems, 1000 per block
#pragma unroll
    for (int r = 0; r < 4; r++) {
        int local = r * 256 + tid;
        if (local < 1000) {
            int g = blockIdx.x * 1000 + local;
            int b = g / A_DIM, e = g % A_DIM;
            float acc = 0.f;
#pragma unroll 10
            for (int s = 0; s < S_LEN; s++)
                acc += attn_sh[s * BATCH + b] * ann[((size_t)s * BATCH + b) * A_DIM + e];
            ctx_out[(size_t)b * C2_DIM + (E_DIM + H_DIM) + e] = acc;
        }
    }
}

// ---------------- per-step: GRU gates + hidden update ----------------
__global__ void gates_kernel(const float* __restrict__ attn,      // (S,B) this step
                             const float* __restrict__ ann_ih,    // (S*B, 3H)
                             const float* __restrict__ gi_e_t,    // (B, 3H) incl b_ih
                             const float* __restrict__ gh,        // (B, 3H)
                             const float* __restrict__ b_hh,
                             const float* __restrict__ hprev,     // (B, H)
                             float* __restrict__ hnew)            // (B, H)
{
    __shared__ float a_sh[S_LEN];
    int b = blockIdx.y;
    int tid = threadIdx.x;
    if (tid < S_LEN) a_sh[tid] = attn[tid * BATCH + b];
    __syncthreads();
    int j = blockIdx.x * 256 + tid;
    if (j >= H_DIM) return;

    float gr = 0.f, gz = 0.f, gn = 0.f;
#pragma unroll 10
    for (int s = 0; s < S_LEN; s++) {
        float a = a_sh[s];
        const float* base = ann_ih + ((size_t)s * BATCH + b) * G_DIM;
        gr += a * base[j];
        gz += a * base[H_DIM + j];
        gn += a * base[2 * H_DIM + j];
    }
    const float* ge = gi_e_t + (size_t)b * G_DIM;
    const float* gb = gh + (size_t)b * G_DIM;
    float hr = gb[j] + b_hh[j];
    float hz = gb[H_DIM + j] + b_hh[H_DIM + j];
    float hn = gb[2 * H_DIM + j] + b_hh[2 * H_DIM + j];
    float r = 1.f / (1.f + __expf(-(ge[j] + gr + hr)));
    float z = 1.f / (1.f + __expf(-(ge[H_DIM + j] + gz + hz)));
    float n = tanhf(ge[2 * H_DIM + j] + gn + r * hn);
    float hp = hprev[(size_t)b * H_DIM + j];
    hnew[(size_t)b * H_DIM + j] = (1.f - z) * n + z * hp;
}

// ---------------- pack h_0..h_48 into comb2 h-columns; emit hidden output ----------------
__global__ void pack_kernel(const float* __restrict__ hbuf,
                            float* __restrict__ comb2,
                            float* __restrict__ hidden)
{
    int i = blockIdx.x * blockDim.x + threadIdx.x;
    if (i < ROWS * H_DIM) {
        int row = i / H_DIM;
        int j = i - row * H_DIM;
        comb2[(size_t)row * C2_DIM + E_DIM + j] = hbuf[i];
    }
    if (i < BATCH * H_DIM)
        hidden[i] = hbuf[(size_t)NSTEPS * BATCH * H_DIM + i];
}

// ---------------- row-wise log-softmax in place (1568 x 30000) ----------------
__global__ void logsoftmax_kernel(float* __restrict__ logits)
{
    int r = blockIdx.x;
    float* p = logits + (size_t)r * V_DIM;
    int tid = threadIdx.x;
    int lane = tid & 31, warp = tid >> 5;
    __shared__ float sh_max[8];
    __shared__ float sh_sum[8];
    __shared__ float bc[2];

    float mx = -1e30f;
    for (int i = tid; i < V_DIM; i += 256) mx = fmaxf(mx, p[i]);
    mx = warp_max(mx);
    if (lane == 0) sh_max[warp] = mx;
    __syncthreads();
    if (tid < 32) {
        float v = (tid < 8) ? sh_max[tid] : -1e30f;
        v = warp_max(v);
        if (tid == 0) bc[0] = v;
    }
    __syncthreads();
    mx = bc[0];

    float sm = 0.f;
    for (int i = tid; i < V_DIM; i += 256) sm += __expf(p[i] - mx);
    sm = warp_sum(sm);
    if (lane == 0) sh_sum[warp] = sm;
    __syncthreads();
    if (tid < 32) {
        float v = (tid < 8) ? sh_sum[tid] : 0.f;
        v = warp_sum(v);
        if (tid == 0) bc[1] = v;
    }
    __syncthreads();
    float lse = mx + logf(bc[1]);

    for (int i = tid; i < V_DIM; i += 256) p[i] -= lse;
}

// ---------------- host launcher ----------------
extern "C" void kernel_launch(void* const* d_in, const int* in_sizes, int n_in,
                              void* d_out, int out_size)
{
    (void)in_sizes; (void)n_in; (void)out_size;
    const int*   tokens = (const int*)  d_in[0];
    const float* ann    = (const float*)d_in[1];
    const float* emb    = (const float*)d_in[2];
    const float* W_h    = (const float*)d_in[3];
    const float* b_h    = (const float*)d_in[4];
    const float* W_c    = (const float*)d_in[5];
    const float* b_c    = (const float*)d_in[6];
    const float* w_a    = (const float*)d_in[7];
    const float* W_ih   = (const float*)d_in[8];
    const float* W_hh   = (const float*)d_in[9];
    const float* b_ih   = (const float*)d_in[10];
    const float* b_hh   = (const float*)d_in[11];
    const float* W_p    = (const float*)d_in[12];
    const float* b_p    = (const float*)d_in[13];

    float* scr = nullptr;
    cudaGetSymbolAddress((void**)&scr, g_scratch);
    float* att_pre = scr + OFF_ATT_PRE;
    float* ann_ih  = scr + OFF_ANN_IH;
    float* gi_e    = scr + OFF_GI_E;
    float* hbuf    = scr + OFF_H;
    float* comb2   = scr + OFF_COMB2;
    float* ubuf    = scr + OFF_U;
    float* ghbuf   = scr + OFF_GH;
    float* scbuf   = scr + OFF_SCORES;

    float* preds  = (float*)d_out;                          // (50, 32, 30000)
    float* hidden = preds + (size_t)T_LEN * BATCH * V_DIM;  // (1, 32, 1000)
    float* attns  = hidden + BATCH * H_DIM;                 // (50, 50, 32)

    // ---- parallel precompute phase ----
    zero_kernel<<<(BATCH * V_DIM + 255) / 256, 256>>>(preds, attns);
    gather_kernel<<<ROWS, 160>>>(tokens, emb, comb2);

    // h0 = tanh(ann[0,:,ECH:] @ W_h.T + b_h)   (32 x 1000, K=1000)
    gemm_tn_kernel<1><<<dim3(8, 1), 256>>>(BATCH, H_DIM, H_DIM,
        ann + ECH, A_DIM, W_h, H_DIM, b_h, hbuf, H_DIM);

    // att_pre = ann @ Wc_a.T + b_c   (1600 x 1000, K=2000); Wc_a = W_c[:,1000:]
    gemm_tn_kernel<0><<<dim3(8, 13), 256>>>(S_LEN * BATCH, H_DIM, A_DIM,
        ann, A_DIM, W_c + H_DIM, H_DIM + A_DIM, b_c, att_pre, H_DIM);

    // ann_ih = ann @ Wih_c.T   (1600 x 3000, K=2000); Wih_c = W_ih[:,620:]
    gemm_tn_kernel<0><<<dim3(24, 13), 256>>>(S_LEN * BATCH, G_DIM, A_DIM,
        ann, A_DIM, W_ih + E_DIM, E_DIM + A_DIM, nullptr, ann_ih, G_DIM);

    // gi_e = emb_rows @ Wih_e.T + b_ih   (1568 x 3000, K=620); emb rows live in comb2
    gemm_tn_kernel<0><<<dim3(24, 13), 256>>>(ROWS, G_DIM, E_DIM,
        comb2, C2_DIM, W_ih, E_DIM + A_DIM, b_ih, gi_e, G_DIM);

    // ---- sequential recurrence ----
    for (int i = 0; i < NSTEPS; i++) {
        float* hprev = hbuf + (size_t)i * BATCH * H_DIM;
        float* hnext = hbuf + (size_t)(i + 1) * BATCH * H_DIM;
        float* attn_t = attns + (size_t)(i + 1) * S_LEN * BATCH;

        hmats_kernel<<<16000, 256>>>(hprev, W_c, W_hh, ubuf, ghbuf);
        scores_kernel<<<200, 256>>>(att_pre, ubuf, w_a, scbuf);
        softmax_ctx_kernel<<<64, 256>>>(scbuf, ann, attn_t,
                                        comb2 + (size_t)i * BATCH * C2_DIM);
        gates_kernel<<<dim3(4, BATCH), 256>>>(attn_t, ann_ih,
                                              gi_e + (size_t)i * BATCH * G_DIM,
                                              ghbuf, b_hh, hprev, hnext);
    }

    // ---- epilogue: pack h, big prediction GEMM, log-softmax ----
    pack_kernel<<<(ROWS * H_DIM + 255) / 256, 256>>>(hbuf, comb2, hidden);

    gemm_tn_kernel<0><<<dim3(235, 13), 256>>>(ROWS, V_DIM, C2_DIM,
        comb2, C2_DIM, W_p, C2_DIM, b_p, preds + (size_t)BATCH * V_DIM, V_DIM);

    logsoftmax_kernel<<<ROWS, 256>>>(preds + (size_t)BATCH * V_DIM);
}

// round 4
// speedup vs baseline: 1.7284x; 1.7284x over previous
#include <cuda_runtime.h>
#include <cuda_bf16.h>
#include <math.h>
#include <stdint.h>

// ---------------- problem constants ----------------
#define S_LEN   50      // SRC
#define T_LEN   50      // TRG
#define BATCH   32
#define E_DIM   620     // EMBED
#define ECH     1000
#define H_DIM   1000    // DCH
#define A_DIM   2000    // 2*ECH
#define V_DIM   30000   // VOCAB
#define G_DIM   3000    // 3*DCH
#define C2_DIM  3620    // E + H + A
#define NSTEPS  49
#define ROWS    (NSTEPS*BATCH)   // 1568

// ---------------- tensor-GEMM tiling ----------------
#define MPAD 1664               // 13 * 128
#define NPAD 30080              // 235 * 128
#define KPAD 3648               // 114 * 32
#define BM   128
#define BN   128
#define BK   32
#define NCHUNK (KPAD/BK)        // 114
#define LDSROW 40               // bf16 elems per smem row (80 B, conflict-free ldmatrix)
#define TILE_BYTES (128*LDSROW*2)       // 10240
#define STAGE_BYTES (4*TILE_BYTES)      // 40960 (Ah,Al,Bh,Bl)
#define GEMM_SMEM (2*STAGE_BYTES)       // 81920

// ---------------- device scratch ----------------
#define OFF_ATT_PRE 0           // (S*B, H)      ann @ Wc_a.T + b_c
#define OFF_ANN_IH  1600000     // (S*B, 3H)     ann @ Wih_c.T
#define OFF_GI_E    6400000     // (ROWS, 3H)    emb[tok] @ Wih_e.T + b_ih
#define OFF_H       11104000    // (50, B, H)    h_0 .. h_49
#define OFF_COMB2   12704000    // (ROWS, 3620)  [emb | h | ctx]
#define OFF_U       18380160    // (B, H)
#define OFF_GH      18412160    // (B, 3H)
#define OFF_SCORES  18508160    // (S, B)
#define SCRATCH_FLOATS 18509760

__device__ __align__(16) float g_scratch[SCRATCH_FLOATS];

// split-bf16 operand buffers for the prediction GEMM
__device__ __align__(16) __nv_bfloat16 g_ah[(size_t)MPAD * KPAD];
__device__ __align__(16) __nv_bfloat16 g_al[(size_t)MPAD * KPAD];
__device__ __align__(16) __nv_bfloat16 g_bh[(size_t)NPAD * KPAD];
__device__ __align__(16) __nv_bfloat16 g_bl[(size_t)NPAD * KPAD];

// ---------------- warp helpers ----------------
__device__ __forceinline__ float warp_sum(float v) {
#pragma unroll
    for (int o = 16; o; o >>= 1) v += __shfl_xor_sync(0xffffffffu, v, o);
    return v;
}
__device__ __forceinline__ float warp_max(float v) {
#pragma unroll
    for (int o = 16; o; o >>= 1) v = fmaxf(v, __shfl_xor_sync(0xffffffffu, v, o));
    return v;
}
__device__ __forceinline__ uint32_t smem_u32(const void* p) {
    uint32_t a;
    asm("{ .reg .u64 t; cvta.to.shared.u64 t, %1; cvt.u32.u64 %0, t; }" : "=r"(a) : "l"(p));
    return a;
}

// ---------------- mma/ldmatrix wrappers (baseline sm_103-legal) ----------------
__device__ __forceinline__ void ldsm_x4(uint32_t* r, uint32_t addr) {
    asm volatile("ldmatrix.sync.aligned.m8n8.x4.shared.b16 {%0,%1,%2,%3}, [%4];"
        : "=r"(r[0]), "=r"(r[1]), "=r"(r[2]), "=r"(r[3]) : "r"(addr));
}
__device__ __forceinline__ void mma_bf16(float* c, const uint32_t* a, const uint32_t* b) {
    asm volatile(
        "mma.sync.aligned.m16n8k16.row.col.f32.bf16.bf16.f32 "
        "{%0,%1,%2,%3}, {%4,%5,%6,%7}, {%8,%9}, {%0,%1,%2,%3};"
        : "+f"(c[0]), "+f"(c[1]), "+f"(c[2]), "+f"(c[3])
        : "r"(a[0]), "r"(a[1]), "r"(a[2]), "r"(a[3]), "r"(b[0]), "r"(b[1]));
}

// ================= split kernels (fp32 -> hi/lo bf16, zero-padded) =================
__global__ void split_a_kernel(const float* __restrict__ src,   // (ROWS, C2_DIM)
                               __nv_bfloat16* __restrict__ hi,
                               __nv_bfloat16* __restrict__ lo)
{
    int i = blockIdx.x * 256 + threadIdx.x;
    if (i >= MPAD * KPAD) return;
    int m = i / KPAD, k = i - m * KPAD;
    float v = (m < ROWS && k < C2_DIM) ? src[(size_t)m * C2_DIM + k] : 0.f;
    __nv_bfloat16 h = __float2bfloat16(v);
    float r = v - __bfloat162float(h);
    hi[i] = h;
    lo[i] = __float2bfloat16(r);
}

__global__ void split_b_kernel(const float* __restrict__ src,   // (V_DIM, C2_DIM)
                               __nv_bfloat16* __restrict__ hi,
                               __nv_bfloat16* __restrict__ lo)
{
    long long i = (long long)blockIdx.x * 256 + threadIdx.x;
    if (i >= (long long)NPAD * KPAD) return;
    int n = (int)(i / KPAD), k = (int)(i - (long long)n * KPAD);
    float v = (n < V_DIM && k < C2_DIM) ? src[(size_t)n * C2_DIM + k] : 0.f;
    __nv_bfloat16 h = __float2bfloat16(v);
    float r = v - __bfloat162float(h);
    hi[i] = h;
    lo[i] = __float2bfloat16(r);
}

// ================= big HMMA GEMM =================
// out[m,n] = sum_k A[m,k]*B[n,k] + bias[n]   via  Ah*Bh + Al*Bh + Ah*Bl
// grid: (13 M-blocks fastest, 235 N-blocks) -> A stays L2-resident, B read ~once.
__global__ __launch_bounds__(256)
void big_gemm_kernel(const float* __restrict__ bias, float* __restrict__ out)
{
    extern __shared__ __align__(16) char smem[];
    const uint32_t sb = smem_u32(smem);
    const int tid = threadIdx.x;
    const int lane = tid & 31;
    const int wid = tid >> 5;
    const int wm = wid & 1;         // 0..1  (64-row half)
    const int wn = wid >> 1;        // 0..3  (32-col quarter)
    const int m0 = blockIdx.x * BM;
    const int n0 = blockIdx.y * BN;

    const __nv_bfloat16* srcs[4] = {
        g_ah + (size_t)m0 * KPAD, g_al + (size_t)m0 * KPAD,
        g_bh + (size_t)n0 * KPAD, g_bl + (size_t)n0 * KPAD
    };

    // per-stage loader: 4 tiles x 128 rows x 64B payload, 80B smem row stride
    auto load_stage = [&](int c, int buf) {
        uint32_t base = sb + buf * STAGE_BYTES;
        int kofs = c * BK;
#pragma unroll
        for (int i = 0; i < 8; i++) {
            int idx = tid + i * 256;            // 0..2047
            int tile = idx >> 9;                // /512
            int rem = idx & 511;
            int row = rem >> 2;
            int seg = rem & 3;
            const char* g = (const char*)(srcs[tile] + (size_t)row * KPAD + kofs) + seg * 16;
            uint32_t so = base + tile * TILE_BYTES + row * (LDSROW * 2) + seg * 16;
            asm volatile("cp.async.cg.shared.global [%0], [%1], 16;\n" :: "r"(so), "l"(g));
        }
        asm volatile("cp.async.commit_group;\n" ::: "memory");
    };

    float acc[4][4][4];
#pragma unroll
    for (int i = 0; i < 4; i++)
#pragma unroll
        for (int j = 0; j < 4; j++)
#pragma unroll
            for (int q = 0; q < 4; q++) acc[i][j][q] = 0.f;

    load_stage(0, 0);

    for (int c = 0; c < NCHUNK; c++) {
        if (c + 1 < NCHUNK) {
            load_stage(c + 1, (c + 1) & 1);
            asm volatile("cp.async.wait_group 1;\n" ::: "memory");
        } else {
            asm volatile("cp.async.wait_group 0;\n" ::: "memory");
        }
        __syncthreads();

        uint32_t st = sb + (c & 1) * STAGE_BYTES;
        uint32_t bAh = st;
        uint32_t bAl = st + TILE_BYTES;
        uint32_t bBh = st + 2 * TILE_BYTES;
        uint32_t bBl = st + 3 * TILE_BYTES;

#pragma unroll
        for (int ks = 0; ks < 2; ks++) {        // two k16 halves of BK=32
            uint32_t ah[4][4], al[4][4], bh[4][2], bl[4][2];

            // A fragments: 4 m-tiles of 16 rows
            int arow = wm * 64 + (lane & 15);
            uint32_t acol = ks * 32 + (lane >> 4) * 16;     // bytes
#pragma unroll
            for (int mt = 0; mt < 4; mt++) {
                uint32_t off = (uint32_t)(arow + mt * 16) * (LDSROW * 2) + acol;
                ldsm_x4(ah[mt], bAh + off);
                ldsm_x4(al[mt], bAl + off);
            }
            // B fragments: x4 covers two 8-col n-tiles
            int brow_base = wn * 32 + (lane & 7) + ((lane >> 4) << 3);
            uint32_t bcol = ks * 32 + ((lane >> 3) & 1) * 16;
#pragma unroll
            for (int np = 0; np < 2; np++) {
                uint32_t r[4];
                uint32_t off = (uint32_t)(brow_base + np * 16) * (LDSROW * 2) + bcol;
                ldsm_x4(r, bBh + off);
                bh[np * 2][0] = r[0]; bh[np * 2][1] = r[1];
                bh[np * 2 + 1][0] = r[2]; bh[np * 2 + 1][1] = r[3];
                ldsm_x4(r, bBl + off);
                bl[np * 2][0] = r[0]; bl[np * 2][1] = r[1];
                bl[np * 2 + 1][0] = r[2]; bl[np * 2 + 1][1] = r[3];
            }
#pragma unroll
            for (int mt = 0; mt < 4; mt++)
#pragma unroll
                for (int nt = 0; nt < 4; nt++) {
                    mma_bf16(acc[mt][nt], ah[mt], bh[nt]);
                    mma_bf16(acc[mt][nt], al[mt], bh[nt]);
                    mma_bf16(acc[mt][nt], ah[mt], bl[nt]);
                }
        }
        __syncthreads();
    }

    // epilogue: +bias, float2 stores (quads of lanes cover full 32B sectors)
#pragma unroll
    for (int mt = 0; mt < 4; mt++) {
#pragma unroll
        for (int nt = 0; nt < 4; nt++) {
            int m = m0 + wm * 64 + mt * 16 + (lane >> 2);
            int n = n0 + wn * 32 + nt * 8 + 2 * (lane & 3);
            if (n < V_DIM) {
                float b0 = bias[n], b1 = bias[n + 1];
                if (m < ROWS) {
                    float2 v = make_float2(acc[mt][nt][0] + b0, acc[mt][nt][1] + b1);
                    *reinterpret_cast<float2*>(out + (size_t)m * V_DIM + n) = v;
                }
                if (m + 8 < ROWS) {
                    float2 v = make_float2(acc[mt][nt][2] + b0, acc[mt][nt][3] + b1);
                    *reinterpret_cast<float2*>(out + (size_t)(m + 8) * V_DIM + n) = v;
                }
            }
        }
    }
}

// ---------------- tiled fp32 GEMM (precompute phase) ----------------
#define GBM 128
#define GBN 128
#define GBK 8

template<int ACT>   // 0 = none, 1 = tanh
__global__ __launch_bounds__(256)
void gemm_tn_kernel(int M, int N, int K,
                    const float* __restrict__ A, int lda,
                    const float* __restrict__ W, int ldw,
                    const float* __restrict__ bias,
                    float* __restrict__ C, int ldc)
{
    __shared__ float As[GBK][GBM + 4];
    __shared__ float Ws[GBK][GBN + 4];

    const int tid = threadIdx.x;
    const int m0 = blockIdx.y * GBM;
    const int n0 = blockIdx.x * GBN;
    const int tx = tid & 15;
    const int ty = tid >> 4;
    const int lm = tid >> 1;
    const int lk = (tid & 1) * 4;

    float acc[8][8];
#pragma unroll
    for (int i = 0; i < 8; i++)
#pragma unroll
        for (int j = 0; j < 8; j++) acc[i][j] = 0.f;

    for (int k0 = 0; k0 < K; k0 += GBK) {
        float4 av = make_float4(0.f, 0.f, 0.f, 0.f);
        if ((m0 + lm) < M && (k0 + lk) < K)
            av = *reinterpret_cast<const float4*>(A + (size_t)(m0 + lm) * lda + k0 + lk);
        As[lk + 0][lm] = av.x; As[lk + 1][lm] = av.y;
        As[lk + 2][lm] = av.z; As[lk + 3][lm] = av.w;

        float4 wv = make_float4(0.f, 0.f, 0.f, 0.f);
        if ((n0 + lm) < N && (k0 + lk) < K)
            wv = *reinterpret_cast<const float4*>(W + (size_t)(n0 + lm) * ldw + k0 + lk);
        Ws[lk + 0][lm] = wv.x; Ws[lk + 1][lm] = wv.y;
        Ws[lk + 2][lm] = wv.z; Ws[lk + 3][lm] = wv.w;

        __syncthreads();

#pragma unroll
        for (int k = 0; k < GBK; k++) {
            float4 a0 = *reinterpret_cast<const float4*>(&As[k][ty * 8]);
            float4 a1 = *reinterpret_cast<const float4*>(&As[k][ty * 8 + 4]);
            float4 b0 = *reinterpret_cast<const float4*>(&Ws[k][tx * 8]);
            float4 b1 = *reinterpret_cast<const float4*>(&Ws[k][tx * 8 + 4]);
            float ar[8] = {a0.x, a0.y, a0.z, a0.w, a1.x, a1.y, a1.z, a1.w};
            float br[8] = {b0.x, b0.y, b0.z, b0.w, b1.x, b1.y, b1.z, b1.w};
#pragma unroll
            for (int i = 0; i < 8; i++)
#pragma unroll
                for (int j = 0; j < 8; j++)
                    acc[i][j] = fmaf(ar[i], br[j], acc[i][j]);
        }
        __syncthreads();
    }

#pragma unroll
    for (int i = 0; i < 8; i++) {
        int m = m0 + ty * 8 + i;
        if (m >= M) continue;
#pragma unroll
        for (int j = 0; j < 8; j++) {
            int n = n0 + tx * 8 + j;
            if (n >= N) continue;
            float v = acc[i][j];
            if (bias) v += bias[n];
            if (ACT == 1) v = tanhf(v);
            C[(size_t)m * ldc + n] = v;
        }
    }
}

// ---------------- init: zero preds[0] and attns[0] ----------------
__global__ void zero_kernel(float* __restrict__ preds, float* __restrict__ attns)
{
    int i = blockIdx.x * blockDim.x + threadIdx.x;
    if (i < BATCH * V_DIM) preds[i] = 0.f;
    if (i < S_LEN * BATCH) attns[i] = 0.f;
}

// ---------------- gather embeddings into comb2 emb columns ----------------
__global__ void gather_kernel(const int* __restrict__ tokens,
                              const float* __restrict__ emb,
                              float* __restrict__ comb2)
{
    int r = blockIdx.x;
    int tok = tokens[r];
    const float4* src = reinterpret_cast<const float4*>(emb + (size_t)tok * E_DIM);
    float4* dst = reinterpret_cast<float4*>(comb2 + (size_t)r * C2_DIM);
    int i = threadIdx.x;
    if (i < E_DIM / 4) dst[i] = src[i];
}

// ---------------- per-step: u = h@Wc_h.T and gh = h@W_hh.T ----------------
__global__ void hmats_kernel(const float* __restrict__ h,
                             const float* __restrict__ W_c,
                             const float* __restrict__ W_hh,
                             float* __restrict__ u,
                             float* __restrict__ gh)
{
    int w = (blockIdx.x * blockDim.x + threadIdx.x) >> 5;
    if (w >= BATCH * (H_DIM + G_DIM)) return;
    int lane = threadIdx.x & 31;
    int b = w / (H_DIM + G_DIM);
    int n = w % (H_DIM + G_DIM);
    const float* a = h + (size_t)b * H_DIM;
    const float* wr;
    float* out;
    if (n < H_DIM) { wr = W_c + (size_t)n * (H_DIM + A_DIM); out = u + (size_t)b * H_DIM + n; }
    else { int j = n - H_DIM; wr = W_hh + (size_t)j * H_DIM; out = gh + (size_t)b * G_DIM + j; }
    float s = 0.f;
    const float4* a4 = reinterpret_cast<const float4*>(a);
    const float4* w4 = reinterpret_cast<const float4*>(wr);
#pragma unroll 2
    for (int i = lane; i < H_DIM / 4; i += 32) {
        float4 x = a4[i], y = w4[i];
        s += x.x * y.x + x.y * y.y + x.z * y.z + x.w * y.w;
    }
    s = warp_sum(s);
    if (lane == 0) *out = s;
}

// ---------------- per-step: scores ----------------
__global__ void scores_kernel(const float* __restrict__ att_pre,
                              const float* __restrict__ u,
                              const float* __restrict__ w_a,
                              float* __restrict__ scores)
{
    int w = (blockIdx.x * blockDim.x + threadIdx.x) >> 5;
    if (w >= S_LEN * BATCH) return;
    int lane = threadIdx.x & 31;
    int b = w & 31;
    const float4* ap = reinterpret_cast<const float4*>(att_pre + (size_t)w * H_DIM);
    const float4* ub = reinterpret_cast<const float4*>(u + (size_t)b * H_DIM);
    const float4* wa = reinterpret_cast<const float4*>(w_a);
    float s = 0.f;
    for (int i = lane; i < H_DIM / 4; i += 32) {
        float4 p = ap[i], q = ub[i], wv = wa[i];
        s += wv.x * tanhf(p.x + q.x) + wv.y * tanhf(p.y + q.y)
           + wv.z * tanhf(p.z + q.z) + wv.w * tanhf(p.w + q.w);
    }
    s = warp_sum(s);
    if (lane == 0) scores[w] = s;
}

// ---------------- per-step: softmax over batch axis + context ----------------
__global__ void softmax_ctx_kernel(const float* __restrict__ scores,
                                   const float* __restrict__ ann,
                                   float* __restrict__ attn_out,
                                   float* __restrict__ ctx_out)
{
    __shared__ float attn_sh[S_LEN * BATCH];
    int tid = threadIdx.x;
    int warp = tid >> 5, lane = tid & 31;

    for (int s = warp; s < S_LEN; s += 8) {
        float v = scores[s * BATCH + lane];
        float mx = warp_max(v);
        float e = __expf(v - mx);
        float sm = warp_sum(e);
        float a = e / sm;
        attn_sh[s * BATCH + lane] = a;
        if (blockIdx.x == 0) attn_out[s * BATCH + lane] = a;
    }
    __syncthreads();

#pragma unroll
    for (int r = 0; r < 4; r++) {
        int local = r * 256 + tid;
        if (local < 1000) {
            int g = blockIdx.x * 1000 + local;
            int b = g / A_DIM, e = g % A_DIM;
            float acc = 0.f;
#pragma unroll 10
            for (int s = 0; s < S_LEN; s++)
                acc += attn_sh[s * BATCH + b] * ann[((size_t)s * BATCH + b) * A_DIM + e];
            ctx_out[(size_t)b * C2_DIM + (E_DIM + H_DIM) + e] = acc;
        }
    }
}

// ---------------- per-step: GRU gates + hidden update ----------------
__global__ void gates_kernel(const float* __restrict__ attn,
                             const float* __restrict__ ann_ih,
                             const float* __restrict__ gi_e_t,
                             const float* __restrict__ gh,
                             const float* __restrict__ b_hh,
                             const float* __restrict__ hprev,
                             float* __restrict__ hnew)
{
    __shared__ float a_sh[S_LEN];
    int b = blockIdx.y;
    int tid = threadIdx.x;
    if (tid < S_LEN) a_sh[tid] = attn[tid * BATCH + b];
    __syncthreads();
    int j = blockIdx.x * 256 + tid;
    if (j >= H_DIM) return;

    float gr = 0.f, gz = 0.f, gn = 0.f;
#pragma unroll 10
    for (int s = 0; s < S_LEN; s++) {
        float a = a_sh[s];
        const float* base = ann_ih + ((size_t)s * BATCH + b) * G_DIM;
        gr += a * base[j];
        gz += a * base[H_DIM + j];
        gn += a * base[2 * H_DIM + j];
    }
    const float* ge = gi_e_t + (size_t)b * G_DIM;
    const float* gb = gh + (size_t)b * G_DIM;
    float hr = gb[j] + b_hh[j];
    float hz = gb[H_DIM + j] + b_hh[H_DIM + j];
    float hn = gb[2 * H_DIM + j] + b_hh[2 * H_DIM + j];
    float r = 1.f / (1.f + __expf(-(ge[j] + gr + hr)));
    float z = 1.f / (1.f + __expf(-(ge[H_DIM + j] + gz + hz)));
    float n = tanhf(ge[2 * H_DIM + j] + gn + r * hn);
    float hp = hprev[(size_t)b * H_DIM + j];
    hnew[(size_t)b * H_DIM + j] = (1.f - z) * n + z * hp;
}

// ---------------- pack h into comb2; emit hidden output ----------------
__global__ void pack_kernel(const float* __restrict__ hbuf,
                            float* __restrict__ comb2,
                            float* __restrict__ hidden)
{
    int i = blockIdx.x * blockDim.x + threadIdx.x;
    if (i < ROWS * H_DIM) {
        int row = i / H_DIM;
        int j = i - row * H_DIM;
        comb2[(size_t)row * C2_DIM + E_DIM + j] = hbuf[i];
    }
    if (i < BATCH * H_DIM)
        hidden[i] = hbuf[(size_t)NSTEPS * BATCH * H_DIM + i];
}

// ---------------- row-wise log-softmax in place ----------------
__global__ void logsoftmax_kernel(float* __restrict__ logits)
{
    int r = blockIdx.x;
    float* p = logits + (size_t)r * V_DIM;
    int tid = threadIdx.x;
    int lane = tid & 31, warp = tid >> 5;
    __shared__ float sh_max[8];
    __shared__ float sh_sum[8];
    __shared__ float bc[2];

    float mx = -1e30f;
    for (int i = tid; i < V_DIM; i += 256) mx = fmaxf(mx, p[i]);
    mx = warp_max(mx);
    if (lane == 0) sh_max[warp] = mx;
    __syncthreads();
    if (tid < 32) {
        float v = (tid < 8) ? sh_max[tid] : -1e30f;
        v = warp_max(v);
        if (tid == 0) bc[0] = v;
    }
    __syncthreads();
    mx = bc[0];

    float sm = 0.f;
    for (int i = tid; i < V_DIM; i += 256) sm += __expf(p[i] - mx);
    sm = warp_sum(sm);
    if (lane == 0) sh_sum[warp] = sm;
    __syncthreads();
    if (tid < 32) {
        float v = (tid < 8) ? sh_sum[tid] : 0.f;
        v = warp_sum(v);
        if (tid == 0) bc[1] = v;
    }
    __syncthreads();
    float lse = mx + logf(bc[1]);

    for (int i = tid; i < V_DIM; i += 256) p[i] -= lse;
}

// ---------------- host launcher ----------------
extern "C" void kernel_launch(void* const* d_in, const int* in_sizes, int n_in,
                              void* d_out, int out_size)
{
    (void)in_sizes; (void)n_in; (void)out_size;
    const int*   tokens = (const int*)  d_in[0];
    const float* ann    = (const float*)d_in[1];
    const float* emb    = (const float*)d_in[2];
    const float* W_h    = (const float*)d_in[3];
    const float* b_h    = (const float*)d_in[4];
    const float* W_c    = (const float*)d_in[5];
    const float* b_c    = (const float*)d_in[6];
    const float* w_a    = (const float*)d_in[7];
    const float* W_ih   = (const float*)d_in[8];
    const float* W_hh   = (const float*)d_in[9];
    const float* b_ih   = (const float*)d_in[10];
    const float* b_hh   = (const float*)d_in[11];
    const float* W_p    = (const float*)d_in[12];
    const float* b_p    = (const float*)d_in[13];

    float* scr = nullptr;
    cudaGetSymbolAddress((void**)&scr, g_scratch);
    __nv_bfloat16 *ah, *al, *bh, *bl;
    cudaGetSymbolAddress((void**)&ah, g_ah);
    cudaGetSymbolAddress((void**)&al, g_al);
    cudaGetSymbolAddress((void**)&bh, g_bh);
    cudaGetSymbolAddress((void**)&bl, g_bl);

    float* att_pre = scr + OFF_ATT_PRE;
    float* ann_ih  = scr + OFF_ANN_IH;
    float* gi_e    = scr + OFF_GI_E;
    float* hbuf    = scr + OFF_H;
    float* comb2   = scr + OFF_COMB2;
    float* ubuf    = scr + OFF_U;
    float* ghbuf   = scr + OFF_GH;
    float* scbuf   = scr + OFF_SCORES;

    float* preds  = (float*)d_out;                          // (50, 32, 30000)
    float* hidden = preds + (size_t)T_LEN * BATCH * V_DIM;  // (1, 32, 1000)
    float* attns  = hidden + BATCH * H_DIM;                 // (50, 50, 32)

    cudaFuncSetAttribute(big_gemm_kernel,
                         cudaFuncAttributeMaxDynamicSharedMemorySize, GEMM_SMEM);

    // ---- parallel precompute phase ----
    zero_kernel<<<(BATCH * V_DIM + 255) / 256, 256>>>(preds, attns);
    gather_kernel<<<ROWS, 160>>>(tokens, emb, comb2);

    // split W_p into bf16 hi/lo (independent of everything else)
    {
        long long total = (long long)NPAD * KPAD;
        int blocks = (int)((total + 255) / 256);
        split_b_kernel<<<blocks, 256>>>(W_p, bh, bl);
    }

    // h0 = tanh(ann[0,:,ECH:] @ W_h.T + b_h)
    gemm_tn_kernel<1><<<dim3(8, 1), 256>>>(BATCH, H_DIM, H_DIM,
        ann + ECH, A_DIM, W_h, H_DIM, b_h, hbuf, H_DIM);

    // att_pre = ann @ Wc_a.T + b_c
    gemm_tn_kernel<0><<<dim3(8, 13), 256>>>(S_LEN * BATCH, H_DIM, A_DIM,
        ann, A_DIM, W_c + H_DIM, H_DIM + A_DIM, b_c, att_pre, H_DIM);

    // ann_ih = ann @ Wih_c.T
    gemm_tn_kernel<0><<<dim3(24, 13), 256>>>(S_LEN * BATCH, G_DIM, A_DIM,
        ann, A_DIM, W_ih + E_DIM, E_DIM + A_DIM, nullptr, ann_ih, G_DIM);

    // gi_e = emb_rows @ Wih_e.T + b_ih   (emb rows live in comb2)
    gemm_tn_kernel<0><<<dim3(24, 13), 256>>>(ROWS, G_DIM, E_DIM,
        comb2, C2_DIM, W_ih, E_DIM + A_DIM, b_ih, gi_e, G_DIM);

    // ---- sequential recurrence ----
    for (int i = 0; i < NSTEPS; i++) {
        float* hprev = hbuf + (size_t)i * BATCH * H_DIM;
        float* hnext = hbuf + (size_t)(i + 1) * BATCH * H_DIM;
        float* attn_t = attns + (size_t)(i + 1) * S_LEN * BATCH;

        hmats_kernel<<<16000, 256>>>(hprev, W_c, W_hh, ubuf, ghbuf);
        scores_kernel<<<200, 256>>>(att_pre, ubuf, w_a, scbuf);
        softmax_ctx_kernel<<<64, 256>>>(scbuf, ann, attn_t,
                                        comb2 + (size_t)i * BATCH * C2_DIM);
        gates_kernel<<<dim3(4, BATCH), 256>>>(attn_t, ann_ih,
                                              gi_e + (size_t)i * BATCH * G_DIM,
                                              ghbuf, b_hh, hprev, hnext);
    }

    // ---- epilogue: pack h, split A, HMMA GEMM (+bias), log-softmax ----
    pack_kernel<<<(ROWS * H_DIM + 255) / 256, 256>>>(hbuf, comb2, hidden);

    split_a_kernel<<<(MPAD * KPAD + 255) / 256, 256>>>(comb2, ah, al);

    big_gemm_kernel<<<dim3(MPAD / BM, NPAD / BN), 256, GEMM_SMEM>>>(
        b_p, preds + (size_t)BATCH * V_DIM);

    logsoftmax_kernel<<<ROWS, 256>>>(preds + (size_t)BATCH * V_DIM);
}

// round 6
// speedup vs baseline: 1.9279x; 1.1154x over previous
#include <cuda_runtime.h>
#include <cuda_bf16.h>
#include <math.h>
#include <stdint.h>

// ---------------- problem constants ----------------
#define S_LEN   50
#define T_LEN   50
#define BATCH   32
#define E_DIM   620
#define ECH     1000
#define H_DIM   1000
#define A_DIM   2000
#define V_DIM   30000
#define G_DIM   3000
#define C2_DIM  3620
#define NSTEPS  49
#define ROWS    (NSTEPS*BATCH)   // 1568

// ug layout: (BATCH, 4096): u in [0,1000), gh in [1024, 4024)
#define UG_LD   4096
#define UG_GH   1024

// ---------------- HMMA tiling ----------------
#define BM   128
#define BN   128
#define BK   32
#define LDSROW 40                        // bf16 per smem row (80 B)
#define TILE_BYTES (128*LDSROW*2)        // 10240
#define STAGE_BYTES (4*TILE_BYTES)       // 40960
#define GEMM_SMEM (2*STAGE_BYTES)        // 81920

// big prediction GEMM padded dims
#define MPAD 1664                        // 13*128
#define NPAD 30080                       // 235*128
#define KPAD 3648                        // 114*32

// ---------------- fp32 scratch ----------------
#define OFF_ATT_PRE 0           // (S*B, H)
#define OFF_ANN_IH  1600000     // (S*B, 3H)
#define OFF_GI_E    6400000     // (ROWS, 3H)
#define OFF_H       11104000    // (50, B, H)
#define OFF_COMB2   12704000    // (ROWS, 3620)
#define OFF_UG      18380160    // (B, 4096)  [u | pad | gh | pad]
#define OFF_SCORES  18511232    // (S, B)
#define SCRATCH_FLOATS 18512832

__device__ __align__(16) float g_scratch[SCRATCH_FLOATS];

// split bf16 hi/lo buffers ([0]=hi, [1]=lo)
__device__ __align__(16) __nv_bfloat16 g_ah[2][(size_t)MPAD * KPAD];
__device__ __align__(16) __nv_bfloat16 g_bh[2][(size_t)NPAD * KPAD];
__device__ __align__(16) __nv_bfloat16 g_annS[2][1664 * 2048];
__device__ __align__(16) __nv_bfloat16 g_wcaS[2][1024 * 2048];
__device__ __align__(16) __nv_bfloat16 g_wihcS[2][3072 * 2048];
__device__ __align__(16) __nv_bfloat16 g_wiheS[2][3072 * 640];
__device__ __align__(16) __nv_bfloat16 g_embS[2][1664 * 640];
__device__ __align__(16) __nv_bfloat16 g_wstepS[2][4096 * 1024];
__device__ __align__(16) __nv_bfloat16 g_hstepS[2][128 * 1024];

// ---------------- helpers ----------------
__device__ __forceinline__ float warp_sum(float v) {
#pragma unroll
    for (int o = 16; o; o >>= 1) v += __shfl_xor_sync(0xffffffffu, v, o);
    return v;
}
__device__ __forceinline__ float warp_max(float v) {
#pragma unroll
    for (int o = 16; o; o >>= 1) v = fmaxf(v, __shfl_xor_sync(0xffffffffu, v, o));
    return v;
}
__device__ __forceinline__ float tanh_fast(float x) {
    float y;
    asm("tanh.approx.f32 %0, %1;" : "=f"(y) : "f"(x));
    return y;
}
__device__ __forceinline__ uint32_t smem_u32(const void* p) {
    uint32_t a;
    asm("{ .reg .u64 t; cvta.to.shared.u64 t, %1; cvt.u32.u64 %0, t; }" : "=r"(a) : "l"(p));
    return a;
}
__device__ __forceinline__ void ldsm_x4(uint32_t* r, uint32_t addr) {
    asm volatile("ldmatrix.sync.aligned.m8n8.x4.shared.b16 {%0,%1,%2,%3}, [%4];"
        : "=r"(r[0]), "=r"(r[1]), "=r"(r[2]), "=r"(r[3]) : "r"(addr));
}
__device__ __forceinline__ void mma_bf16(float* c, const uint32_t* a, const uint32_t* b) {
    asm volatile(
        "mma.sync.aligned.m16n8k16.row.col.f32.bf16.bf16.f32 "
        "{%0,%1,%2,%3}, {%4,%5,%6,%7}, {%8,%9}, {%0,%1,%2,%3};"
        : "+f"(c[0]), "+f"(c[1]), "+f"(c[2]), "+f"(c[3])
        : "r"(a[0]), "r"(a[1]), "r"(a[2]), "r"(a[3]), "r"(b[0]), "r"(b[1]));
}

// ================= generic split: fp32 (M,K) -> zero-padded bf16 hi/lo ====
__global__ void split_gen(const float* __restrict__ src, int ldsrc, int M, int K, int Kp,
                          __nv_bfloat16* __restrict__ hi, __nv_bfloat16* __restrict__ lo)
{
    int k = blockIdx.x * 256 + threadIdx.x;
    int m = blockIdx.y;
    if (k >= Kp) return;
    float v = (m < M && k < K) ? src[(size_t)m * ldsrc + k] : 0.f;
    __nv_bfloat16 h = __float2bfloat16(v);
    size_t o = (size_t)m * Kp + k;
    hi[o] = h;
    lo[o] = __float2bfloat16(v - __bfloat162float(h));
}

// ================= generic split-bf16 HMMA GEMM ==================================
// out[m,n] = A[m,:].B[n,:] + bias[n]   computed as Ah*Bh + Al*Bh + Ah*Bl
__global__ __launch_bounds__(256)
void hmma_gemm(const __nv_bfloat16* __restrict__ Ah, const __nv_bfloat16* __restrict__ Al,
               const __nv_bfloat16* __restrict__ Bh, const __nv_bfloat16* __restrict__ Bl,
               int ldka, int ldkb, int kchunks,
               const float* __restrict__ bias, float* __restrict__ out, int ldo,
               int Mlim, int Nlim)
{
    extern __shared__ __align__(16) char smem[];
    const uint32_t sb = smem_u32(smem);
    const int tid = threadIdx.x;
    const int lane = tid & 31;
    const int wid = tid >> 5;
    const int wm = wid & 1;
    const int wn = wid >> 1;
    const int m0 = blockIdx.x * BM;
    const int n0 = blockIdx.y * BN;

    const __nv_bfloat16* srcs[4] = {
        Ah + (size_t)m0 * ldka, Al + (size_t)m0 * ldka,
        Bh + (size_t)n0 * ldkb, Bl + (size_t)n0 * ldkb
    };
    const int lds[4] = { ldka, ldka, ldkb, ldkb };

    auto load_stage = [&](int c, int buf) {
        uint32_t base = sb + buf * STAGE_BYTES;
        int kofs = c * BK;
#pragma unroll
        for (int i = 0; i < 8; i++) {
            int idx = tid + i * 256;
            int tile = idx >> 9;
            int rem = idx & 511;
            int row = rem >> 2;
            int seg = rem & 3;
            const char* g = (const char*)(srcs[tile] + (size_t)row * lds[tile] + kofs) + seg * 16;
            uint32_t so = base + tile * TILE_BYTES + row * (LDSROW * 2) + seg * 16;
            asm volatile("cp.async.cg.shared.global [%0], [%1], 16;\n" :: "r"(so), "l"(g));
        }
        asm volatile("cp.async.commit_group;\n" ::: "memory");
    };

    float acc[4][4][4];
#pragma unroll
    for (int i = 0; i < 4; i++)
#pragma unroll
        for (int j = 0; j < 4; j++)
#pragma unroll
            for (int q = 0; q < 4; q++) acc[i][j][q] = 0.f;

    load_stage(0, 0);

    for (int c = 0; c < kchunks; c++) {
        if (c + 1 < kchunks) {
            load_stage(c + 1, (c + 1) & 1);
            asm volatile("cp.async.wait_group 1;\n" ::: "memory");
        } else {
            asm volatile("cp.async.wait_group 0;\n" ::: "memory");
        }
        __syncthreads();

        uint32_t st = sb + (c & 1) * STAGE_BYTES;
        uint32_t bAh = st;
        uint32_t bAl = st + TILE_BYTES;
        uint32_t bBh = st + 2 * TILE_BYTES;
        uint32_t bBl = st + 3 * TILE_BYTES;

#pragma unroll
        for (int ks = 0; ks < 2; ks++) {
            uint32_t ah[4][4], al[4][4], bh[4][2], bl[4][2];

            int arow = wm * 64 + (lane & 15);
            uint32_t acol = ks * 32 + (lane >> 4) * 16;
#pragma unroll
            for (int mt = 0; mt < 4; mt++) {
                uint32_t off = (uint32_t)(arow + mt * 16) * (LDSROW * 2) + acol;
                ldsm_x4(ah[mt], bAh + off);
                ldsm_x4(al[mt], bAl + off);
            }
            int brow_base = wn * 32 + (lane & 7) + ((lane >> 4) << 3);
            uint32_t bcol = ks * 32 + ((lane >> 3) & 1) * 16;
#pragma unroll
            for (int np = 0; np < 2; np++) {
                uint32_t r[4];
                uint32_t off = (uint32_t)(brow_base + np * 16) * (LDSROW * 2) + bcol;
                ldsm_x4(r, bBh + off);
                bh[np * 2][0] = r[0]; bh[np * 2][1] = r[1];
                bh[np * 2 + 1][0] = r[2]; bh[np * 2 + 1][1] = r[3];
                ldsm_x4(r, bBl + off);
                bl[np * 2][0] = r[0]; bl[np * 2][1] = r[1];
                bl[np * 2 + 1][0] = r[2]; bl[np * 2 + 1][1] = r[3];
            }
#pragma unroll
            for (int mt = 0; mt < 4; mt++)
#pragma unroll
                for (int nt = 0; nt < 4; nt++) {
                    mma_bf16(acc[mt][nt], ah[mt], bh[nt]);
                    mma_bf16(acc[mt][nt], al[mt], bh[nt]);
                    mma_bf16(acc[mt][nt], ah[mt], bl[nt]);
                }
        }
        __syncthreads();
    }

#pragma unroll
    for (int mt = 0; mt < 4; mt++) {
#pragma unroll
        for (int nt = 0; nt < 4; nt++) {
            int m = m0 + wm * 64 + mt * 16 + (lane >> 2);
            int n = n0 + wn * 32 + nt * 8 + 2 * (lane & 3);
            if (n < Nlim) {
                float b0 = 0.f, b1 = 0.f;
                if (bias) { b0 = bias[n]; b1 = bias[n + 1]; }
                if (m < Mlim) {
                    float2 v = make_float2(acc[mt][nt][0] + b0, acc[mt][nt][1] + b1);
                    *reinterpret_cast<float2*>(out + (size_t)m * ldo + n) = v;
                }
                if (m + 8 < Mlim) {
                    float2 v = make_float2(acc[mt][nt][2] + b0, acc[mt][nt][3] + b1);
                    *reinterpret_cast<float2*>(out + (size_t)(m + 8) * ldo + n) = v;
                }
            }
        }
    }
}

// ---------------- init kernels ----------------
__global__ void zero_kernel(float* __restrict__ preds, float* __restrict__ attns)
{
    int i = blockIdx.x * blockDim.x + threadIdx.x;
    if (i < BATCH * V_DIM) preds[i] = 0.f;
    if (i < S_LEN * BATCH) attns[i] = 0.f;
}

__global__ void zero_hstep(__nv_bfloat16* __restrict__ hi, __nv_bfloat16* __restrict__ lo)
{
    int i = blockIdx.x * 256 + threadIdx.x;
    if (i < 128 * 1024) { hi[i] = __float2bfloat16(0.f); lo[i] = __float2bfloat16(0.f); }
}

// ---------------- gather embeddings into comb2 emb columns ----------------
__global__ void gather_kernel(const int* __restrict__ tokens,
                              const float* __restrict__ emb,
                              float* __restrict__ comb2)
{
    int r = blockIdx.x;
    int tok = tokens[r];
    const float4* src = reinterpret_cast<const float4*>(emb + (size_t)tok * E_DIM);
    float4* dst = reinterpret_cast<float4*>(comb2 + (size_t)r * C2_DIM);
    int i = threadIdx.x;
    if (i < E_DIM / 4) dst[i] = src[i];
}

// ---------------- h0 = tanh(ann[0,:,ECH:] @ W_h.T + b_h); also split to bf16 ----------------
__global__ void h0_kernel(const float* __restrict__ ann, const float* __restrict__ W_h,
                          const float* __restrict__ b_h, float* __restrict__ hbuf,
                          __nv_bfloat16* __restrict__ hhi, __nv_bfloat16* __restrict__ hlo)
{
    int w = (blockIdx.x * 256 + threadIdx.x) >> 5;
    if (w >= BATCH * H_DIM) return;
    int lane = threadIdx.x & 31;
    int b = w / H_DIM, n = w - b * H_DIM;
    const float4* a4 = reinterpret_cast<const float4*>(ann + (size_t)b * A_DIM + ECH);
    const float4* w4 = reinterpret_cast<const float4*>(W_h + (size_t)n * H_DIM);
    float s = 0.f;
    for (int i = lane; i < H_DIM / 4; i += 32) {
        float4 x = a4[i], y = w4[i];
        s += x.x * y.x + x.y * y.y + x.z * y.z + x.w * y.w;
    }
    s = warp_sum(s);
    if (lane == 0) {
        float v = tanh_fast(s + b_h[n]);
        hbuf[b * H_DIM + n] = v;
        __nv_bfloat16 h = __float2bfloat16(v);
        hhi[b * 1024 + n] = h;
        hlo[b * 1024 + n] = __float2bfloat16(v - __bfloat162float(h));
    }
}

// ---------------- per-step: scores[s,b] = w_a . tanh(att_pre[s,b,:] + u[b,:]) ----------------
__global__ void scores_kernel(const float* __restrict__ att_pre,
                              const float* __restrict__ ug,     // (B, UG_LD), u = cols [0,1000)
                              const float* __restrict__ w_a,
                              float* __restrict__ scores)
{
    int w = (blockIdx.x * blockDim.x + threadIdx.x) >> 5;
    if (w >= S_LEN * BATCH) return;
    int lane = threadIdx.x & 31;
    int b = w & 31;
    const float4* ap = reinterpret_cast<const float4*>(att_pre + (size_t)w * H_DIM);
    const float4* ub = reinterpret_cast<const float4*>(ug + (size_t)b * UG_LD);
    const float4* wa = reinterpret_cast<const float4*>(w_a);
    float s = 0.f;
    for (int i = lane; i < H_DIM / 4; i += 32) {
        float4 p = ap[i], q = ub[i], wv = wa[i];
        s += wv.x * tanh_fast(p.x + q.x) + wv.y * tanh_fast(p.y + q.y)
           + wv.z * tanh_fast(p.z + q.z) + wv.w * tanh_fast(p.w + q.w);
    }
    s = warp_sum(s);
    if (lane == 0) scores[w] = s;
}

// ---------------- per-step: softmax over batch axis + context into comb2 ----------------
__global__ void softmax_ctx_kernel(const float* __restrict__ scores,
                                   const float* __restrict__ ann,
                                   float* __restrict__ attn_out,
                                   float* __restrict__ ctx_out)
{
    __shared__ float attn_sh[S_LEN * BATCH];
    int tid = threadIdx.x;
    int warp = tid >> 5, lane = tid & 31;

    for (int s = warp; s < S_LEN; s += 8) {
        float v = scores[s * BATCH + lane];
        float mx = warp_max(v);
        float e = __expf(v - mx);
        float sm = warp_sum(e);
        float a = e / sm;
        attn_sh[s * BATCH + lane] = a;
        if (blockIdx.x == 0) attn_out[s * BATCH + lane] = a;
    }
    __syncthreads();

#pragma unroll
    for (int r = 0; r < 4; r++) {
        int local = r * 256 + tid;
        if (local < 1000) {
            int g = blockIdx.x * 1000 + local;
            int b = g / A_DIM, e = g % A_DIM;
            float acc = 0.f;
#pragma unroll 10
            for (int s = 0; s < S_LEN; s++)
                acc += attn_sh[s * BATCH + b] * ann[((size_t)s * BATCH + b) * A_DIM + e];
            ctx_out[(size_t)b * C2_DIM + (E_DIM + H_DIM) + e] = acc;
        }
    }
}

// ---------------- per-step: GRU gates + hidden update; also split hnew ----------------
__global__ void gates_kernel(const float* __restrict__ attn,
                             const float* __restrict__ ann_ih,
                             const float* __restrict__ gi_e_t,
                             const float* __restrict__ ug,      // gh at cols [UG_GH, UG_GH+3000)
                             const float* __restrict__ b_hh,
                             const float* __restrict__ hprev,
                             float* __restrict__ hnew,
                             __nv_bfloat16* __restrict__ hhi,
                             __nv_bfloat16* __restrict__ hlo)
{
    __shared__ float a_sh[S_LEN];
    int b = blockIdx.y;
    int tid = threadIdx.x;
    if (tid < S_LEN) a_sh[tid] = attn[tid * BATCH + b];
    __syncthreads();
    int j = blockIdx.x * 256 + tid;
    if (j >= H_DIM) return;

    float gr = 0.f, gz = 0.f, gn = 0.f;
#pragma unroll 10
    for (int s = 0; s < S_LEN; s++) {
        float a = a_sh[s];
        const float* base = ann_ih + ((size_t)s * BATCH + b) * G_DIM;
        gr += a * base[j];
        gz += a * base[H_DIM + j];
        gn += a * base[2 * H_DIM + j];
    }
    const float* ge = gi_e_t + (size_t)b * G_DIM;
    const float* gb = ug + (size_t)b * UG_LD + UG_GH;
    float hr = gb[j] + b_hh[j];
    float hz = gb[H_DIM + j] + b_hh[H_DIM + j];
    float hn = gb[2 * H_DIM + j] + b_hh[2 * H_DIM + j];
    float r = 1.f / (1.f + __expf(-(ge[j] + gr + hr)));
    float z = 1.f / (1.f + __expf(-(ge[H_DIM + j] + gz + hz)));
    float n = tanh_fast(ge[2 * H_DIM + j] + gn + r * hn);
    float hp = hprev[(size_t)b * H_DIM + j];
    float v = (1.f - z) * n + z * hp;
    hnew[(size_t)b * H_DIM + j] = v;
    __nv_bfloat16 h = __float2bfloat16(v);
    hhi[b * 1024 + j] = h;
    hlo[b * 1024 + j] = __float2bfloat16(v - __bfloat162float(h));
}

// ---------------- pack h into comb2; emit hidden output ----------------
__global__ void pack_kernel(const float* __restrict__ hbuf,
                            float* __restrict__ comb2,
                            float* __restrict__ hidden)
{
    int i = blockIdx.x * blockDim.x + threadIdx.x;
    if (i < ROWS * H_DIM) {
        int row = i / H_DIM;
        int j = i - row * H_DIM;
        comb2[(size_t)row * C2_DIM + E_DIM + j] = hbuf[i];
    }
    if (i < BATCH * H_DIM)
        hidden[i] = hbuf[(size_t)NSTEPS * BATCH * H_DIM + i];
}

// ---------------- row-wise log-softmax in place ----------------
__global__ void logsoftmax_kernel(float* __restrict__ logits)
{
    int r = blockIdx.x;
    float* p = logits + (size_t)r * V_DIM;
    int tid = threadIdx.x;
    int lane = tid & 31, warp = tid >> 5;
    __shared__ float sh_max[8];
    __shared__ float sh_sum[8];
    __shared__ float bc[2];

    float mx = -1e30f;
    for (int i = tid; i < V_DIM; i += 256) mx = fmaxf(mx, p[i]);
    mx = warp_max(mx);
    if (lane == 0) sh_max[warp] = mx;
    __syncthreads();
    if (tid < 32) {
        float v = (tid < 8) ? sh_max[tid] : -1e30f;
        v = warp_max(v);
        if (tid == 0) bc[0] = v;
    }
    __syncthreads();
    mx = bc[0];

    float sm = 0.f;
    for (int i = tid; i < V_DIM; i += 256) sm += __expf(p[i] - mx);
    sm = warp_sum(sm);
    if (lane == 0) sh_sum[warp] = sm;
    __syncthreads();
    if (tid < 32) {
        float v = (tid < 8) ? sh_sum[tid] : 0.f;
        v = warp_sum(v);
        if (tid == 0) bc[1] = v;
    }
    __syncthreads();
    float lse = mx + logf(bc[1]);

    for (int i = tid; i < V_DIM; i += 256) p[i] -= lse;
}

// ---------------- host launcher ----------------
extern "C" void kernel_launch(void* const* d_in, const int* in_sizes, int n_in,
                              void* d_out, int out_size)
{
    (void)in_sizes; (void)n_in; (void)out_size;
    const int*   tokens = (const int*)  d_in[0];
    const float* ann    = (const float*)d_in[1];
    const float* emb    = (const float*)d_in[2];
    const float* W_h    = (const float*)d_in[3];
    const float* b_h    = (const float*)d_in[4];
    const float* W_c    = (const float*)d_in[5];
    const float* b_c    = (const float*)d_in[6];
    const float* w_a    = (const float*)d_in[7];
    const float* W_ih   = (const float*)d_in[8];
    const float* W_hh   = (const float*)d_in[9];
    const float* b_ih   = (const float*)d_in[10];
    const float* b_hh   = (const float*)d_in[11];
    const float* W_p    = (const float*)d_in[12];
    const float* b_p    = (const float*)d_in[13];

    float* scr = nullptr;
    cudaGetSymbolAddress((void**)&scr, g_scratch);
    __nv_bfloat16 *ah, *bh, *annS, *wcaS, *wihcS, *wiheS, *embS, *wstepS, *hstepS;
    cudaGetSymbolAddress((void**)&ah,     g_ah);
    cudaGetSymbolAddress((void**)&bh,     g_bh);
    cudaGetSymbolAddress((void**)&annS,   g_annS);
    cudaGetSymbolAddress((void**)&wcaS,   g_wcaS);
    cudaGetSymbolAddress((void**)&wihcS,  g_wihcS);
    cudaGetSymbolAddress((void**)&wiheS,  g_wiheS);
    cudaGetSymbolAddress((void**)&embS,   g_embS);
    cudaGetSymbolAddress((void**)&wstepS, g_wstepS);
    cudaGetSymbolAddress((void**)&hstepS, g_hstepS);

    const size_t AH_SZ = (size_t)MPAD * KPAD;
    const size_t BH_SZ = (size_t)NPAD * KPAD;
    __nv_bfloat16* ahL = ah + AH_SZ;
    __nv_bfloat16* bhL = bh + BH_SZ;
    __nv_bfloat16* annL  = annS  + (size_t)1664 * 2048;
    __nv_bfloat16* wcaL  = wcaS  + (size_t)1024 * 2048;
    __nv_bfloat16* wihcL = wihcS + (size_t)3072 * 2048;
    __nv_bfloat16* wiheL = wiheS + (size_t)3072 * 640;
    __nv_bfloat16* embL  = embS  + (size_t)1664 * 640;
    __nv_bfloat16* wstL  = wstepS + (size_t)4096 * 1024;
    __nv_bfloat16* hstL  = hstepS + (size_t)128 * 1024;

    float* att_pre = scr + OFF_ATT_PRE;
    float* ann_ih  = scr + OFF_ANN_IH;
    float* gi_e    = scr + OFF_GI_E;
    float* hbuf    = scr + OFF_H;
    float* comb2   = scr + OFF_COMB2;
    float* ug      = scr + OFF_UG;
    float* scbuf   = scr + OFF_SCORES;

    float* preds  = (float*)d_out;
    float* hidden = preds + (size_t)T_LEN * BATCH * V_DIM;
    float* attns  = hidden + BATCH * H_DIM;

    cudaFuncSetAttribute(hmma_gemm,
                         cudaFuncAttributeMaxDynamicSharedMemorySize, GEMM_SMEM);

    // ---- init + splits (parallel phase) ----
    zero_kernel<<<(BATCH * V_DIM + 255) / 256, 256>>>(preds, attns);
    zero_hstep<<<512, 256>>>(hstepS, hstL);
    gather_kernel<<<ROWS, 160>>>(tokens, emb, comb2);

    split_gen<<<dim3(15, NPAD), 256>>>(W_p, C2_DIM, V_DIM, C2_DIM, KPAD, bh, bhL);
    split_gen<<<dim3(8, 1664), 256>>>(ann, A_DIM, S_LEN * BATCH, A_DIM, 2048, annS, annL);
    split_gen<<<dim3(8, 1024), 256>>>(W_c + H_DIM, H_DIM + A_DIM, H_DIM, A_DIM, 2048, wcaS, wcaL);
    split_gen<<<dim3(8, 3072), 256>>>(W_ih + E_DIM, E_DIM + A_DIM, G_DIM, A_DIM, 2048, wihcS, wihcL);
    split_gen<<<dim3(3, 3072), 256>>>(W_ih, E_DIM + A_DIM, G_DIM, E_DIM, 640, wiheS, wiheL);
    split_gen<<<dim3(3, 1664), 256>>>(comb2, C2_DIM, ROWS, E_DIM, 640, embS, embL);
    // step-weight stack: rows [0,1024) = Wc_h (1000 valid), rows [1024,4096) = W_hh (3000 valid)
    split_gen<<<dim3(4, 1024), 256>>>(W_c, H_DIM + A_DIM, H_DIM, H_DIM, 1024,
                                      wstepS, wstL);
    split_gen<<<dim3(4, 3072), 256>>>(W_hh, H_DIM, G_DIM, H_DIM, 1024,
                                      wstepS + (size_t)1024 * 1024, wstL + (size_t)1024 * 1024);

    // h0
    h0_kernel<<<4000, 256>>>(ann, W_h, b_h, hbuf, hstepS, hstL);

    // ---- precompute GEMMs (HMMA) ----
    hmma_gemm<<<dim3(13, 8), 256, GEMM_SMEM>>>(annS, annL, wcaS, wcaL,
        2048, 2048, 64, b_c, att_pre, H_DIM, S_LEN * BATCH, H_DIM);
    hmma_gemm<<<dim3(13, 24), 256, GEMM_SMEM>>>(annS, annL, wihcS, wihcL,
        2048, 2048, 64, nullptr, ann_ih, G_DIM, S_LEN * BATCH, G_DIM);
    hmma_gemm<<<dim3(13, 24), 256, GEMM_SMEM>>>(embS, embL, wiheS, wiheL,
        640, 640, 20, b_ih, gi_e, G_DIM, ROWS, G_DIM);

    // ---- sequential recurrence ----
    for (int i = 0; i < NSTEPS; i++) {
        float* hprev = hbuf + (size_t)i * BATCH * H_DIM;
        float* hnext = hbuf + (size_t)(i + 1) * BATCH * H_DIM;
        float* attn_t = attns + (size_t)(i + 1) * S_LEN * BATCH;

        // ug = h @ [Wc_h | W_hh].T   (32 x 4096 padded, K=1024)
        // output column n == stacked-weight padded row n: u at [0,1000), gh at [1024,4024)
        hmma_gemm<<<dim3(1, 32), 256, GEMM_SMEM>>>(hstepS, hstL, wstepS, wstL,
            1024, 1024, 32, nullptr, ug, UG_LD, BATCH, UG_LD);
        scores_kernel<<<200, 256>>>(att_pre, ug, w_a, scbuf);
        softmax_ctx_kernel<<<64, 256>>>(scbuf, ann, attn_t,
                                        comb2 + (size_t)i * BATCH * C2_DIM);
        gates_kernel<<<dim3(4, BATCH), 256>>>(attn_t, ann_ih,
                                              gi_e + (size_t)i * BATCH * G_DIM,
                                              ug, b_hh, hprev, hnext, hstepS, hstL);
    }

    // ---- epilogue ----
    pack_kernel<<<(ROWS * H_DIM + 255) / 256, 256>>>(hbuf, comb2, hidden);
    split_gen<<<dim3(15, 1664), 256>>>(comb2, C2_DIM, ROWS, C2_DIM, KPAD, ah, ahL);

    hmma_gemm<<<dim3(13, 235), 256, GEMM_SMEM>>>(ah, ahL, bh, bhL,
        KPAD, KPAD, KPAD / BK, b_p, preds + (size_t)BATCH * V_DIM, V_DIM, ROWS, V_DIM);

    logsoftmax_kernel<<<ROWS, 256>>>(preds + (size_t)BATCH * V_DIM);
}